// round 4
// baseline (speedup 1.0000x reference)
#include <cuda_runtime.h>
#include <math.h>

#define NB 8
#define SEQL 8192
#define CDIM 384
#define DH 128
#define LMK 64
#define NCH 64              // split-N chunks for kernel_3 (8192/64 = 128 keys/chunk)
#define RSCALE 0.05103103630798288f   // 1/sqrt(384)

// ---------------- device scratch (no runtime allocation) ----------------
__device__ float g_q[NB * SEQL * DH];
__device__ float g_k[NB * SEQL * DH];
__device__ float g_v[NB * SEQL * DH];
__device__ float g_qlm[NB * LMK * DH];
__device__ float g_klm[NB * LMK * DH];
__device__ float g_k2[NB * LMK * LMK];     // kernel_2 (row softmax)
__device__ float g_kinv[NB * LMK * LMK];   // Newton-Schulz pseudo-inverse
__device__ float g_ps[NB * NCH * LMK * DH];
__device__ float g_pm[NB * NCH * LMK];
__device__ float g_pz[NB * NCH * LMK];
__device__ float g_G[NB * LMK * DH];       // kinv @ (kernel_3 @ v)
__device__ float g_pwT[DH * DH];           // proj_w transposed

// =========================================================================
// 1) qkv = x @ qkv_w^T : M=65536, N=384, K=384. 128x128 tile, BK=16,
//    256 threads, 8x8 microtile. blockIdx.y selects q/k/v section.
// =========================================================================
__global__ void __launch_bounds__(256) k_qkv(const float* __restrict__ x,
                                             const float* __restrict__ w) {
    __shared__ float As[16 * 132];
    __shared__ float Ws[16 * 132];
    const int tid = threadIdx.x;
    const int tx = tid & 15, ty = tid >> 4;
    const long row0 = (long)blockIdx.x * 128;
    const int sec = blockIdx.y;
    const int wrow0 = sec * 128;

    float acc[8][8];
#pragma unroll
    for (int i = 0; i < 8; i++)
#pragma unroll
        for (int j = 0; j < 8; j++) acc[i][j] = 0.f;

    for (int kt = 0; kt < CDIM; kt += 16) {
#pragma unroll
        for (int i = 0; i < 2; i++) {
            int p = tid + i * 256;
            int r = p >> 2, c4 = (p & 3) * 4;
            float4 a = *(const float4*)(x + (row0 + r) * CDIM + kt + c4);
            As[(c4 + 0) * 132 + r] = a.x;
            As[(c4 + 1) * 132 + r] = a.y;
            As[(c4 + 2) * 132 + r] = a.z;
            As[(c4 + 3) * 132 + r] = a.w;
            float4 b = *(const float4*)(w + (wrow0 + r) * CDIM + kt + c4);
            Ws[(c4 + 0) * 132 + r] = b.x;
            Ws[(c4 + 1) * 132 + r] = b.y;
            Ws[(c4 + 2) * 132 + r] = b.z;
            Ws[(c4 + 3) * 132 + r] = b.w;
        }
        __syncthreads();
#pragma unroll
        for (int k = 0; k < 16; k++) {
            float a[8], b[8];
            *(float4*)(a)     = *(float4*)&As[k * 132 + ty * 8];
            *(float4*)(a + 4) = *(float4*)&As[k * 132 + ty * 8 + 4];
            *(float4*)(b)     = *(float4*)&Ws[k * 132 + tx * 8];
            *(float4*)(b + 4) = *(float4*)&Ws[k * 132 + tx * 8 + 4];
#pragma unroll
            for (int i = 0; i < 8; i++)
#pragma unroll
                for (int j = 0; j < 8; j++) acc[i][j] += a[i] * b[j];
        }
        __syncthreads();
    }
    float* dst = sec == 0 ? g_q : (sec == 1 ? g_k : g_v);
    const float scale = sec == 0 ? RSCALE : 1.0f;
#pragma unroll
    for (int i = 0; i < 8; i++) {
        long m = row0 + ty * 8 + i;
        float4 o0, o1;
        o0.x = acc[i][0] * scale; o0.y = acc[i][1] * scale;
        o0.z = acc[i][2] * scale; o0.w = acc[i][3] * scale;
        o1.x = acc[i][4] * scale; o1.y = acc[i][5] * scale;
        o1.z = acc[i][6] * scale; o1.w = acc[i][7] * scale;
        *(float4*)&dst[m * DH + tx * 8]     = o0;
        *(float4*)&dst[m * DH + tx * 8 + 4] = o1;
    }
}

// =========================================================================
// 2) landmark means: 512 blocks (b,l), 128 threads (d). seg = 128.
// =========================================================================
__global__ void k_lm() {
    int b = blockIdx.x >> 6, l = blockIdx.x & 63;
    int d = threadIdx.x;
    const float* kp = g_k + ((long)(b * SEQL + l * 128)) * DH + d;
    const float* qp = g_q + ((long)(b * SEQL + l * 128)) * DH + d;
    float sk = 0.f, sq = 0.f;
    for (int i = 0; i < 128; i++) { sk += kp[i * DH]; sq += qp[i * DH]; }
    g_klm[(b * LMK + l) * DH + d] = sk * (1.f / 128.f);
    g_qlm[(b * LMK + l) * DH + d] = sq * (1.f / 128.f);
}

// =========================================================================
// 3) proj_w transpose (one-time, tiny)
// =========================================================================
__global__ void k_pwT(const float* __restrict__ pw) {
    int e = blockIdx.x, d = threadIdx.x;
    g_pwT[e * DH + d] = pw[d * DH + e];
}

// =========================================================================
// 4) kernel_2 softmax + Newton-Schulz inverse. 8 blocks x 512 threads.
//    Per thread: 2 rows x 4 cols of every 64x64 matmul (b-side float4).
//    smem: sV + sA + sT = exactly 48 KB.
// =========================================================================
__global__ void __launch_bounds__(512) k_newton() {
    __shared__ float sV[4096], sA[4096], sT[4096];
    const int b = blockIdx.x, t = threadIdx.x;
    const int j4 = (t & 15) * 4;
    const int i2 = (t >> 4) * 2;

    // S = qlm @ klm^T
    {
        const float* qb = g_qlm + b * LMK * DH;
        const float* kb = g_klm + b * LMK * DH;
        float a[2][4] = {{0,0,0,0},{0,0,0,0}};
        for (int d4 = 0; d4 < DH; d4 += 4) {
            float4 q0 = *(const float4*)(qb + i2 * DH + d4);
            float4 q1 = *(const float4*)(qb + (i2 + 1) * DH + d4);
#pragma unroll
            for (int jj = 0; jj < 4; jj++) {
                float4 kv = *(const float4*)(kb + (j4 + jj) * DH + d4);
                a[0][jj] += q0.x*kv.x + q0.y*kv.y + q0.z*kv.z + q0.w*kv.w;
                a[1][jj] += q1.x*kv.x + q1.y*kv.y + q1.z*kv.z + q1.w*kv.w;
            }
        }
#pragma unroll
        for (int ii = 0; ii < 2; ii++)
#pragma unroll
            for (int jj = 0; jj < 4; jj++) sA[(i2 + ii) * 64 + j4 + jj] = a[ii][jj];
    }
    __syncthreads();
    // row softmax (16 warps x 4 rows)
    {
        int w = t >> 5, lane = t & 31;
        for (int rr = 0; rr < 4; rr++) {
            int r = w * 4 + rr;
            float v0 = sA[r * 64 + lane], v1 = sA[r * 64 + 32 + lane];
            float m = fmaxf(v0, v1);
            for (int o = 16; o; o >>= 1) m = fmaxf(m, __shfl_xor_sync(0xffffffffu, m, o));
            v0 = __expf(v0 - m); v1 = __expf(v1 - m);
            float s = v0 + v1;
            for (int o = 16; o; o >>= 1) s += __shfl_xor_sync(0xffffffffu, s, o);
            float inv = 1.f / s;
            sA[r * 64 + lane] = v0 * inv;
            sA[r * 64 + 32 + lane] = v1 * inv;
        }
    }
    __syncthreads();
    // write K to global, column sums, denominator
    float* Kg = g_k2 + b * 4096;
    for (int e = t; e < 4096; e += 512) Kg[e] = sA[e];
    if (t < 64) {
        float c = 0.f;
        for (int i = 0; i < 64; i++) c += sA[i * 64 + t];
        sT[t] = c;
    }
    __syncthreads();
    if (t == 0) {
        float m = sT[0];
        for (int j = 1; j < 64; j++) m = fmaxf(m, sT[j]);
        sT[0] = m;
    }
    __syncthreads();
    float rdenom = 1.f / sT[0];
    __syncthreads();
    // V0 = K^T / denom
    for (int e = t; e < 4096; e += 512) {
        int i = e >> 6, j = e & 63;
        sV[e] = sA[j * 64 + i] * rdenom;
    }
    __syncthreads();

    for (int it = 0; it < 6; it++) {
        float a[2][4];
        // A = K @ V  (K from global, broadcast via L1)
#pragma unroll
        for (int ii = 0; ii < 2; ii++)
#pragma unroll
            for (int jj = 0; jj < 4; jj++) a[ii][jj] = 0.f;
        for (int k = 0; k < 64; k++) {
            float k0 = Kg[i2 * 64 + k], k1 = Kg[(i2 + 1) * 64 + k];
            float4 bv = *(float4*)&sV[k * 64 + j4];
            a[0][0] += k0 * bv.x; a[0][1] += k0 * bv.y; a[0][2] += k0 * bv.z; a[0][3] += k0 * bv.w;
            a[1][0] += k1 * bv.x; a[1][1] += k1 * bv.y; a[1][2] += k1 * bv.z; a[1][3] += k1 * bv.w;
        }
#pragma unroll
        for (int ii = 0; ii < 2; ii++)
#pragma unroll
            for (int jj = 0; jj < 4; jj++) sA[(i2 + ii) * 64 + j4 + jj] = a[ii][jj];
        __syncthreads();
        // T1 = 7A - A@A -> sT
#pragma unroll
        for (int ii = 0; ii < 2; ii++)
#pragma unroll
            for (int jj = 0; jj < 4; jj++) a[ii][jj] = 0.f;
        for (int k = 0; k < 64; k++) {
            float a0 = sA[i2 * 64 + k], a1 = sA[(i2 + 1) * 64 + k];
            float4 bv = *(float4*)&sA[k * 64 + j4];
            a[0][0] += a0 * bv.x; a[0][1] += a0 * bv.y; a[0][2] += a0 * bv.z; a[0][3] += a0 * bv.w;
            a[1][0] += a1 * bv.x; a[1][1] += a1 * bv.y; a[1][2] += a1 * bv.z; a[1][3] += a1 * bv.w;
        }
#pragma unroll
        for (int ii = 0; ii < 2; ii++)
#pragma unroll
            for (int jj = 0; jj < 4; jj++)
                sT[(i2 + ii) * 64 + j4 + jj] = 7.f * sA[(i2 + ii) * 64 + j4 + jj] - a[ii][jj];
        __syncthreads();
        // T2 = 15A - A@T1 -> sT (register-staged overwrite)
#pragma unroll
        for (int ii = 0; ii < 2; ii++)
#pragma unroll
            for (int jj = 0; jj < 4; jj++) a[ii][jj] = 0.f;
        for (int k = 0; k < 64; k++) {
            float a0 = sA[i2 * 64 + k], a1 = sA[(i2 + 1) * 64 + k];
            float4 bv = *(float4*)&sT[k * 64 + j4];
            a[0][0] += a0 * bv.x; a[0][1] += a0 * bv.y; a[0][2] += a0 * bv.z; a[0][3] += a0 * bv.w;
            a[1][0] += a1 * bv.x; a[1][1] += a1 * bv.y; a[1][2] += a1 * bv.z; a[1][3] += a1 * bv.w;
        }
#pragma unroll
        for (int ii = 0; ii < 2; ii++)
#pragma unroll
            for (int jj = 0; jj < 4; jj++)
                a[ii][jj] = 15.f * sA[(i2 + ii) * 64 + j4 + jj] - a[ii][jj];
        __syncthreads();
#pragma unroll
        for (int ii = 0; ii < 2; ii++)
#pragma unroll
            for (int jj = 0; jj < 4; jj++) sT[(i2 + ii) * 64 + j4 + jj] = a[ii][jj];
        __syncthreads();
        // V = 0.25*(13V - V@T2) -> sV (register-staged overwrite)
#pragma unroll
        for (int ii = 0; ii < 2; ii++)
#pragma unroll
            for (int jj = 0; jj < 4; jj++) a[ii][jj] = 0.f;
        for (int k = 0; k < 64; k++) {
            float v0 = sV[i2 * 64 + k], v1 = sV[(i2 + 1) * 64 + k];
            float4 bv = *(float4*)&sT[k * 64 + j4];
            a[0][0] += v0 * bv.x; a[0][1] += v0 * bv.y; a[0][2] += v0 * bv.z; a[0][3] += v0 * bv.w;
            a[1][0] += v1 * bv.x; a[1][1] += v1 * bv.y; a[1][2] += v1 * bv.z; a[1][3] += v1 * bv.w;
        }
#pragma unroll
        for (int ii = 0; ii < 2; ii++)
#pragma unroll
            for (int jj = 0; jj < 4; jj++)
                a[ii][jj] = 0.25f * (13.f * sV[(i2 + ii) * 64 + j4 + jj] - a[ii][jj]);
        __syncthreads();
#pragma unroll
        for (int ii = 0; ii < 2; ii++)
#pragma unroll
            for (int jj = 0; jj < 4; jj++) sV[(i2 + ii) * 64 + j4 + jj] = a[ii][jj];
        __syncthreads();
    }
    for (int e = t; e < 4096; e += 512) g_kinv[b * 4096 + e] = sV[e];
}

// =========================================================================
// 5) kernel_3 split-N partials with online softmax. grid (8, 64), 256 thr.
//    chunk = 128 keys, 4 subtiles of 32. qlm tile in smem.
// =========================================================================
__global__ void __launch_bounds__(256) k_partial() {
    __shared__ float sQ[LMK * DH];     // 32 KB
    __shared__ float sS[LMK * 32];     // 8 KB
    __shared__ float sM[LMK], sZ[LMK], sFac[LMK];
    const int b = blockIdx.x, c = blockIdx.y;
    const int t = threadIdx.x;
    for (int e = t; e < LMK * DH; e += 256) sQ[e] = g_qlm[b * LMK * DH + e];
    if (t < 64) { sM[t] = -1e30f; sZ[t] = 0.f; }
    __syncthreads();

    float acc[32];
#pragma unroll
    for (int i = 0; i < 32; i++) acc[i] = 0.f;
    const int d = t & 127, half = t >> 7;
    const int jkey = t & 31, wl = (t >> 5) * 8;
    const float* kb = g_k + ((long)b * SEQL + c * 128) * DH;
    const float* vb = g_v + ((long)b * SEQL + c * 128) * DH;

    for (int tt = 0; tt < 4; tt++) {
        // scores: warp wl rows x key jkey
        float s[8];
#pragma unroll
        for (int r = 0; r < 8; r++) s[r] = 0.f;
        const float* krow = kb + (tt * 32 + jkey) * DH;
        for (int d4 = 0; d4 < DH; d4 += 4) {
            float4 kv = *(const float4*)(krow + d4);
#pragma unroll
            for (int r = 0; r < 8; r++) {
                float4 qv = *(const float4*)&sQ[(wl + r) * DH + d4];
                s[r] += qv.x*kv.x + qv.y*kv.y + qv.z*kv.z + qv.w*kv.w;
            }
        }
        __syncthreads();   // prior tile's accumulate done reading sS/sFac
#pragma unroll
        for (int r = 0; r < 8; r++) {
            int l = wl + r;
            float mt = s[r];
            for (int o = 16; o; o >>= 1) mt = fmaxf(mt, __shfl_xor_sync(0xffffffffu, mt, o));
            float mold = sM[l];
            float mnew = fmaxf(mold, mt);
            float p = __expf(s[r] - mnew);
            float ps = p;
            for (int o = 16; o; o >>= 1) ps += __shfl_xor_sync(0xffffffffu, ps, o);
            if (jkey == 0) {
                float fac = __expf(mold - mnew);
                sFac[l] = fac;
                sZ[l] = sZ[l] * fac + ps;
                sM[l] = mnew;
            }
            sS[l * 32 + jkey] = p;
        }
        __syncthreads();
        // accumulate: thread (d, half) owns 32 l-rows
        const float* vt = vb + tt * 32 * DH;
#pragma unroll
        for (int la = 0; la < 32; la++) acc[la] *= sFac[half * 32 + la];
        for (int k4 = 0; k4 < 32; k4 += 4) {
            float v0 = vt[(k4 + 0) * DH + d];
            float v1 = vt[(k4 + 1) * DH + d];
            float v2 = vt[(k4 + 2) * DH + d];
            float v3 = vt[(k4 + 3) * DH + d];
#pragma unroll
            for (int la = 0; la < 32; la++) {
                float4 pv = *(float4*)&sS[(half * 32 + la) * 32 + k4];
                acc[la] += pv.x * v0 + pv.y * v1 + pv.z * v2 + pv.w * v3;
            }
        }
    }
    long base = ((long)(b * NCH + c) * LMK) * DH;
#pragma unroll
    for (int la = 0; la < 32; la++)
        g_ps[base + (half * 32 + la) * DH + d] = acc[la];
    if (t < 64) {
        g_pm[(b * NCH + c) * LMK + t] = sM[t];
        g_pz[(b * NCH + c) * LMK + t] = sZ[t];
    }
}

// =========================================================================
// 6) combine partials -> F, then G = kinv @ F. 8 blocks x 256 threads.
//    smem: sWt 16KB + sF 32KB = 48KB exactly.
// =========================================================================
__global__ void __launch_bounds__(256) k_combine() {
    __shared__ float sWt[NCH * LMK];
    __shared__ float sF[LMK * DH];
    const int b = blockIdx.x, t = threadIdx.x;
    if (t < 64) {
        int l = t;
        float M = -1e30f;
        for (int c = 0; c < NCH; c++) M = fmaxf(M, g_pm[(b * NCH + c) * LMK + l]);
        float Z = 0.f;
        for (int c = 0; c < NCH; c++)
            Z += g_pz[(b * NCH + c) * LMK + l] * __expf(g_pm[(b * NCH + c) * LMK + l] - M);
        float rZ = 1.f / Z;
        for (int c = 0; c < NCH; c++)
            sWt[c * LMK + l] = __expf(g_pm[(b * NCH + c) * LMK + l] - M) * rZ;
    }
    __syncthreads();
    const int d = t & 127, half = t >> 7;
    for (int la = 0; la < 32; la++) {
        int l = half * 32 + la;
        float acc = 0.f;
        for (int c = 0; c < NCH; c++)
            acc += g_ps[(((long)(b * NCH + c)) * LMK + l) * DH + d] * sWt[c * LMK + l];
        sF[l * DH + d] = acc;
    }
    __syncthreads();
    const float* inv = g_kinv + b * 4096;
    for (int la = 0; la < 32; la++) {
        int l = half * 32 + la;
        float acc = 0.f;
        for (int j = 0; j < 64; j++) acc += inv[l * 64 + j] * sF[j * DH + d];
        g_G[((long)b * LMK + l) * DH + d] = acc;
    }
}

// =========================================================================
// 7) fused epilogue: kernel_1 softmax -> @G -> proj -> +bias -> +v residual.
//    1024 blocks x 256 threads, 64 rows/block. smem 32KB + 16KB = 48KB.
// =========================================================================
__global__ void __launch_bounds__(256) k_out(const float* __restrict__ pb,
                                             float* __restrict__ out) {
    __shared__ float sQ[LMK * DH];   // q tile, later reused for o
    __shared__ float sP[LMK * LMK];
    const int bid = blockIdx.x;
    const int b = bid >> 7;
    const int n0 = (bid & 127) * 64;
    const int t = threadIdx.x;
    const long rowbase = (long)b * SEQL + n0;

    for (int e = t; e < LMK * DH; e += 256) sQ[e] = g_q[rowbase * DH + e];
    __syncthreads();
    // scores (kernel_1 logits): thread (l = t&63, rg = t>>6) -> 16 rows
    {
        const int l = t & 63, rg = t >> 6;
        const float* krow = g_klm + ((long)b * LMK + l) * DH;
        float s[16];
#pragma unroll
        for (int r = 0; r < 16; r++) s[r] = 0.f;
        for (int d4 = 0; d4 < DH; d4 += 4) {
            float4 kv = *(const float4*)(krow + d4);
#pragma unroll
            for (int r = 0; r < 16; r++) {
                float4 qv = *(const float4*)&sQ[(rg * 16 + r) * DH + d4];
                s[r] += qv.x*kv.x + qv.y*kv.y + qv.z*kv.z + qv.w*kv.w;
            }
        }
#pragma unroll
        for (int r = 0; r < 16; r++) sP[(rg * 16 + r) * 64 + l] = s[r];
    }
    __syncthreads();
    // row softmax: 8 warps x 8 rows
    {
        const int w = t >> 5, lane = t & 31;
        for (int rr = 0; rr < 8; rr++) {
            int r = w * 8 + rr;
            float v0 = sP[r * 64 + lane], v1 = sP[r * 64 + 32 + lane];
            float m = fmaxf(v0, v1);
            for (int o = 16; o; o >>= 1) m = fmaxf(m, __shfl_xor_sync(0xffffffffu, m, o));
            v0 = __expf(v0 - m); v1 = __expf(v1 - m);
            float s = v0 + v1;
            for (int o = 16; o; o >>= 1) s += __shfl_xor_sync(0xffffffffu, s, o);
            float inv = 1.f / s;
            sP[r * 64 + lane] = v0 * inv;
            sP[r * 64 + 32 + lane] = v1 * inv;
        }
    }
    __syncthreads();
    // o = P @ G : thread (d = t&127, half) owns 32 rows
    const int d = t & 127, half = t >> 7;
    float o[32];
#pragma unroll
    for (int la = 0; la < 32; la++) o[la] = 0.f;
    const float* Gb = g_G + (long)b * LMK * DH;
    for (int l4 = 0; l4 < 64; l4 += 4) {
        float g0 = Gb[(l4 + 0) * DH + d];
        float g1 = Gb[(l4 + 1) * DH + d];
        float g2 = Gb[(l4 + 2) * DH + d];
        float g3 = Gb[(l4 + 3) * DH + d];
#pragma unroll
        for (int la = 0; la < 32; la++) {
            float4 pv = *(float4*)&sP[(half * 32 + la) * 64 + l4];
            o[la] += pv.x * g0 + pv.y * g1 + pv.z * g2 + pv.w * g3;
        }
    }
    __syncthreads();   // last sQ read was in score phase, already fenced
#pragma unroll
    for (int la = 0; la < 32; la++) sQ[(half * 32 + la) * DH + d] = o[la];
    __syncthreads();
    // proj: y = o @ proj_w^T using pwT (pw[d][e] = pwT[e][d])
    float y[32];
#pragma unroll
    for (int la = 0; la < 32; la++) y[la] = 0.f;
    for (int e4 = 0; e4 < DH; e4 += 4) {
        float w0 = g_pwT[(e4 + 0) * DH + d];
        float w1 = g_pwT[(e4 + 1) * DH + d];
        float w2 = g_pwT[(e4 + 2) * DH + d];
        float w3 = g_pwT[(e4 + 3) * DH + d];
#pragma unroll
        for (int la = 0; la < 32; la++) {
            float4 ov = *(float4*)&sQ[(half * 32 + la) * DH + e4];
            y[la] += ov.x * w0 + ov.y * w1 + ov.z * w2 + ov.w * w3;
        }
    }
    const float bias = pb[d];
#pragma unroll
    for (int la = 0; la < 32; la++) {
        long n = rowbase + half * 32 + la;
        out[n * DH + d] = g_v[n * DH + d] + y[la] + bias;
    }
}

// =========================================================================
extern "C" void kernel_launch(void* const* d_in, const int* in_sizes, int n_in,
                              void* d_out, int out_size) {
    const float* x      = (const float*)d_in[0];
    const float* qkv_w  = (const float*)d_in[1];
    const float* proj_w = (const float*)d_in[2];
    const float* proj_b = (const float*)d_in[3];
    float* out = (float*)d_out;

    k_qkv<<<dim3(512, 3), 256>>>(x, qkv_w);
    k_lm<<<512, 128>>>();
    k_pwT<<<128, 128>>>(proj_w);
    k_newton<<<8, 512>>>();
    k_partial<<<dim3(8, NCH), 256>>>();
    k_combine<<<8, 256>>>();
    k_out<<<1024, 256>>>(proj_b, out);
}

// round 6
// speedup vs baseline: 1.0840x; 1.0840x over previous
#include <cuda_runtime.h>
#include <math.h>

#define NB 8
#define SEQL 8192
#define CDIM 384
#define DH 128
#define LMK 64
#define NCH 64              // split-N chunks for kernel_3 (8192/64 = 128 keys/chunk)
#define RSCALE 0.05103103630798288f   // 1/sqrt(384)

// ---------------- device scratch (no runtime allocation) ----------------
__device__ float g_q[NB * SEQL * DH];
__device__ float g_k[NB * SEQL * DH];
__device__ float g_v[NB * SEQL * DH];
__device__ float g_qlm[NB * LMK * DH];
__device__ float g_klm[NB * LMK * DH];
__device__ float g_k2[NB * LMK * LMK];     // kernel_2 (row softmax)
__device__ float g_kinv[NB * LMK * LMK];   // Newton-Schulz pseudo-inverse
__device__ float g_ps[NB * NCH * LMK * DH];
__device__ float g_pm[NB * NCH * LMK];
__device__ float g_pz[NB * NCH * LMK];
__device__ float g_G[NB * LMK * DH];       // kinv @ (kernel_3 @ v)
__device__ float g_pwT[DH * DH];           // proj_w transposed

// =========================================================================
// 1) qkv = x @ qkv_w^T : M=65536, N=384, K=384. 128x128 tile, BK=16,
//    256 threads, 8x8 microtile. blockIdx.y selects q/k/v section.
// =========================================================================
__global__ void __launch_bounds__(256) k_qkv(const float* __restrict__ x,
                                             const float* __restrict__ w) {
    __shared__ float As[16 * 132];
    __shared__ float Ws[16 * 132];
    const int tid = threadIdx.x;
    const int tx = tid & 15, ty = tid >> 4;
    const long row0 = (long)blockIdx.x * 128;
    const int sec = blockIdx.y;
    const int wrow0 = sec * 128;

    float acc[8][8];
#pragma unroll
    for (int i = 0; i < 8; i++)
#pragma unroll
        for (int j = 0; j < 8; j++) acc[i][j] = 0.f;

    for (int kt = 0; kt < CDIM; kt += 16) {
#pragma unroll
        for (int i = 0; i < 2; i++) {
            int p = tid + i * 256;
            int r = p >> 2, c4 = (p & 3) * 4;
            float4 a = *(const float4*)(x + (row0 + r) * CDIM + kt + c4);
            As[(c4 + 0) * 132 + r] = a.x;
            As[(c4 + 1) * 132 + r] = a.y;
            As[(c4 + 2) * 132 + r] = a.z;
            As[(c4 + 3) * 132 + r] = a.w;
            float4 b = *(const float4*)(w + (wrow0 + r) * CDIM + kt + c4);
            Ws[(c4 + 0) * 132 + r] = b.x;
            Ws[(c4 + 1) * 132 + r] = b.y;
            Ws[(c4 + 2) * 132 + r] = b.z;
            Ws[(c4 + 3) * 132 + r] = b.w;
        }
        __syncthreads();
#pragma unroll
        for (int k = 0; k < 16; k++) {
            float a[8], b[8];
            *(float4*)(a)     = *(float4*)&As[k * 132 + ty * 8];
            *(float4*)(a + 4) = *(float4*)&As[k * 132 + ty * 8 + 4];
            *(float4*)(b)     = *(float4*)&Ws[k * 132 + tx * 8];
            *(float4*)(b + 4) = *(float4*)&Ws[k * 132 + tx * 8 + 4];
#pragma unroll
            for (int i = 0; i < 8; i++)
#pragma unroll
                for (int j = 0; j < 8; j++) acc[i][j] += a[i] * b[j];
        }
        __syncthreads();
    }
    float* dst = sec == 0 ? g_q : (sec == 1 ? g_k : g_v);
    const float scale = sec == 0 ? RSCALE : 1.0f;
#pragma unroll
    for (int i = 0; i < 8; i++) {
        long m = row0 + ty * 8 + i;
        float4 o0, o1;
        o0.x = acc[i][0] * scale; o0.y = acc[i][1] * scale;
        o0.z = acc[i][2] * scale; o0.w = acc[i][3] * scale;
        o1.x = acc[i][4] * scale; o1.y = acc[i][5] * scale;
        o1.z = acc[i][6] * scale; o1.w = acc[i][7] * scale;
        *(float4*)&dst[m * DH + tx * 8]     = o0;
        *(float4*)&dst[m * DH + tx * 8 + 4] = o1;
    }
}

// =========================================================================
// 2) landmark means: 512 blocks (b,l), 128 threads (d). seg = 128.
// =========================================================================
__global__ void k_lm() {
    int b = blockIdx.x >> 6, l = blockIdx.x & 63;
    int d = threadIdx.x;
    const float* kp = g_k + ((long)(b * SEQL + l * 128)) * DH + d;
    const float* qp = g_q + ((long)(b * SEQL + l * 128)) * DH + d;
    float sk = 0.f, sq = 0.f;
    for (int i = 0; i < 128; i++) { sk += kp[i * DH]; sq += qp[i * DH]; }
    g_klm[(b * LMK + l) * DH + d] = sk * (1.f / 128.f);
    g_qlm[(b * LMK + l) * DH + d] = sq * (1.f / 128.f);
}

// =========================================================================
// 3) proj_w transpose (one-time, tiny)
// =========================================================================
__global__ void k_pwT(const float* __restrict__ pw) {
    int e = blockIdx.x, d = threadIdx.x;
    g_pwT[e * DH + d] = pw[d * DH + e];
}

// =========================================================================
// 64x64 matmul fragment: 4 rows x 4 cols per thread, 256 threads.
// Arow: row-major 64x64 (global or shared). B: row-major 64x64 (shared).
// =========================================================================
__device__ __forceinline__ void mm64(const float* Arow, const float* B,
                                     int i4, int j4, float a[4][4]) {
#pragma unroll
    for (int ii = 0; ii < 4; ii++)
#pragma unroll
        for (int jj = 0; jj < 4; jj++) a[ii][jj] = 0.f;
    for (int k = 0; k < 64; k++) {
        float4 bv = *(const float4*)&B[k * 64 + j4];
        float a0 = Arow[(i4 + 0) * 64 + k];
        float a1 = Arow[(i4 + 1) * 64 + k];
        float a2 = Arow[(i4 + 2) * 64 + k];
        float a3 = Arow[(i4 + 3) * 64 + k];
        a[0][0] += a0 * bv.x; a[0][1] += a0 * bv.y; a[0][2] += a0 * bv.z; a[0][3] += a0 * bv.w;
        a[1][0] += a1 * bv.x; a[1][1] += a1 * bv.y; a[1][2] += a1 * bv.z; a[1][3] += a1 * bv.w;
        a[2][0] += a2 * bv.x; a[2][1] += a2 * bv.y; a[2][2] += a2 * bv.z; a[2][3] += a2 * bv.w;
        a[3][0] += a3 * bv.x; a[3][1] += a3 * bv.y; a[3][2] += a3 * bv.z; a[3][3] += a3 * bv.w;
    }
}

// =========================================================================
// 4) FUSED mid-stage: grid (8, NCH+1), 256 threads, 48KB dynamic smem.
//    blockIdx.y <  NCH : kernel_3 split-N flash partial for chunk y.
//    blockIdx.y == NCH : kernel_2 softmax + Newton-Schulz inverse (batch x).
//    Independent work overlapped in ONE launch — no streams, graph-safe.
// =========================================================================
__global__ void __launch_bounds__(256) k_mid() {
    extern __shared__ float sm[];
    const int b = blockIdx.x;
    const int t = threadIdx.x;

    if (blockIdx.y == NCH) {
        // ---------------- Newton-Schulz path (4 rows x 4 cols / thread) ----
        float* sV = sm;            // 4096
        float* sA = sm + 4096;     // 4096
        float* sT = sm + 8192;     // 4096
        const int j4 = (t & 15) * 4;
        const int i4 = (t >> 4) * 4;

        // S = qlm @ klm^T
        {
            const float* qb = g_qlm + b * LMK * DH;
            const float* kb = g_klm + b * LMK * DH;
            float a[4][4];
#pragma unroll
            for (int ii = 0; ii < 4; ii++)
#pragma unroll
                for (int jj = 0; jj < 4; jj++) a[ii][jj] = 0.f;
            for (int d4 = 0; d4 < DH; d4 += 4) {
                float4 kv[4];
#pragma unroll
                for (int jj = 0; jj < 4; jj++)
                    kv[jj] = *(const float4*)(kb + (j4 + jj) * DH + d4);
#pragma unroll
                for (int ii = 0; ii < 4; ii++) {
                    float4 qv = *(const float4*)(qb + (i4 + ii) * DH + d4);
#pragma unroll
                    for (int jj = 0; jj < 4; jj++)
                        a[ii][jj] += qv.x*kv[jj].x + qv.y*kv[jj].y + qv.z*kv[jj].z + qv.w*kv[jj].w;
                }
            }
#pragma unroll
            for (int ii = 0; ii < 4; ii++)
#pragma unroll
                for (int jj = 0; jj < 4; jj++) sA[(i4 + ii) * 64 + j4 + jj] = a[ii][jj];
        }
        __syncthreads();
        // row softmax: 8 warps x 8 rows
        {
            int w = t >> 5, lane = t & 31;
            for (int rr = 0; rr < 8; rr++) {
                int r = w * 8 + rr;
                float v0 = sA[r * 64 + lane], v1 = sA[r * 64 + 32 + lane];
                float m = fmaxf(v0, v1);
                for (int o = 16; o; o >>= 1) m = fmaxf(m, __shfl_xor_sync(0xffffffffu, m, o));
                v0 = __expf(v0 - m); v1 = __expf(v1 - m);
                float s = v0 + v1;
                for (int o = 16; o; o >>= 1) s += __shfl_xor_sync(0xffffffffu, s, o);
                float inv = 1.f / s;
                sA[r * 64 + lane] = v0 * inv;
                sA[r * 64 + 32 + lane] = v1 * inv;
            }
        }
        __syncthreads();
        float* Kg = g_k2 + b * 4096;
        for (int e = t; e < 4096; e += 256) Kg[e] = sA[e];
        if (t < 64) {
            float c = 0.f;
            for (int i = 0; i < 64; i++) c += sA[i * 64 + t];
            sT[t] = c;
        }
        __syncthreads();
        if (t == 0) {
            float m = sT[0];
            for (int j = 1; j < 64; j++) m = fmaxf(m, sT[j]);
            sT[0] = m;
        }
        __syncthreads();
        float rdenom = 1.f / sT[0];
        __syncthreads();
        for (int e = t; e < 4096; e += 256) {
            int i = e >> 6, j = e & 63;
            sV[e] = sA[j * 64 + i] * rdenom;
        }
        __syncthreads();

        float a[4][4];
        for (int it = 0; it < 6; it++) {
            // A = K @ V
            mm64(Kg, sV, i4, j4, a);
#pragma unroll
            for (int ii = 0; ii < 4; ii++)
#pragma unroll
                for (int jj = 0; jj < 4; jj++) sA[(i4 + ii) * 64 + j4 + jj] = a[ii][jj];
            __syncthreads();
            // T = 7A - A@A
            mm64(sA, sA, i4, j4, a);
#pragma unroll
            for (int ii = 0; ii < 4; ii++)
#pragma unroll
                for (int jj = 0; jj < 4; jj++)
                    sT[(i4 + ii) * 64 + j4 + jj] = 7.f * sA[(i4 + ii) * 64 + j4 + jj] - a[ii][jj];
            __syncthreads();
            // T = 15A - A@T  (register-staged overwrite)
            mm64(sA, sT, i4, j4, a);
#pragma unroll
            for (int ii = 0; ii < 4; ii++)
#pragma unroll
                for (int jj = 0; jj < 4; jj++)
                    a[ii][jj] = 15.f * sA[(i4 + ii) * 64 + j4 + jj] - a[ii][jj];
            __syncthreads();
#pragma unroll
            for (int ii = 0; ii < 4; ii++)
#pragma unroll
                for (int jj = 0; jj < 4; jj++) sT[(i4 + ii) * 64 + j4 + jj] = a[ii][jj];
            __syncthreads();
            // V = 0.25*(13V - V@T)
            mm64(sV, sT, i4, j4, a);
#pragma unroll
            for (int ii = 0; ii < 4; ii++)
#pragma unroll
                for (int jj = 0; jj < 4; jj++)
                    a[ii][jj] = 0.25f * (13.f * sV[(i4 + ii) * 64 + j4 + jj] - a[ii][jj]);
            __syncthreads();
#pragma unroll
            for (int ii = 0; ii < 4; ii++)
#pragma unroll
                for (int jj = 0; jj < 4; jj++) sV[(i4 + ii) * 64 + j4 + jj] = a[ii][jj];
            __syncthreads();
        }
        for (int e = t; e < 4096; e += 256) g_kinv[b * 4096 + e] = sV[e];
        return;
    }

    // ---------------- flash partial path (chunk c = blockIdx.y) ------------
    float* sQ   = sm;              // 8192 floats
    float* sS   = sm + 8192;       // 2048
    float* sM   = sm + 10240;      // 64
    float* sZ   = sm + 10304;      // 64
    float* sFac = sm + 10368;      // 64
    const int c = blockIdx.y;
    for (int e = t; e < LMK * DH; e += 256) sQ[e] = g_qlm[b * LMK * DH + e];
    if (t < 64) { sM[t] = -1e30f; sZ[t] = 0.f; }
    __syncthreads();

    float acc[32];
#pragma unroll
    for (int i = 0; i < 32; i++) acc[i] = 0.f;
    const int d = t & 127, half = t >> 7;
    const int jkey = t & 31, wl = (t >> 5) * 8;
    const float* kb = g_k + ((long)b * SEQL + c * 128) * DH;
    const float* vb = g_v + ((long)b * SEQL + c * 128) * DH;

    for (int tt = 0; tt < 4; tt++) {
        float s[8];
#pragma unroll
        for (int r = 0; r < 8; r++) s[r] = 0.f;
        const float* krow = kb + (tt * 32 + jkey) * DH;
        for (int d4 = 0; d4 < DH; d4 += 4) {
            float4 kv = *(const float4*)(krow + d4);
#pragma unroll
            for (int r = 0; r < 8; r++) {
                float4 qv = *(const float4*)&sQ[(wl + r) * DH + d4];
                s[r] += qv.x*kv.x + qv.y*kv.y + qv.z*kv.z + qv.w*kv.w;
            }
        }
        __syncthreads();   // prior tile's accumulate done reading sS/sFac
#pragma unroll
        for (int r = 0; r < 8; r++) {
            int l = wl + r;
            float mt = s[r];
            for (int o = 16; o; o >>= 1) mt = fmaxf(mt, __shfl_xor_sync(0xffffffffu, mt, o));
            float mold = sM[l];
            float mnew = fmaxf(mold, mt);
            float p = __expf(s[r] - mnew);
            float ps = p;
            for (int o = 16; o; o >>= 1) ps += __shfl_xor_sync(0xffffffffu, ps, o);
            if (jkey == 0) {
                float fac = __expf(mold - mnew);
                sFac[l] = fac;
                sZ[l] = sZ[l] * fac + ps;
                sM[l] = mnew;
            }
            sS[l * 32 + jkey] = p;
        }
        __syncthreads();
        const float* vt = vb + tt * 32 * DH;
#pragma unroll
        for (int la = 0; la < 32; la++) acc[la] *= sFac[half * 32 + la];
        for (int k4 = 0; k4 < 32; k4 += 4) {
            float v0 = vt[(k4 + 0) * DH + d];
            float v1 = vt[(k4 + 1) * DH + d];
            float v2 = vt[(k4 + 2) * DH + d];
            float v3 = vt[(k4 + 3) * DH + d];
#pragma unroll
            for (int la = 0; la < 32; la++) {
                float4 pv = *(float4*)&sS[(half * 32 + la) * 32 + k4];
                acc[la] += pv.x * v0 + pv.y * v1 + pv.z * v2 + pv.w * v3;
            }
        }
    }
    long base = ((long)(b * NCH + c) * LMK) * DH;
#pragma unroll
    for (int la = 0; la < 32; la++)
        g_ps[base + (half * 32 + la) * DH + d] = acc[la];
    if (t < 64) {
        g_pm[(b * NCH + c) * LMK + t] = sM[t];
        g_pz[(b * NCH + c) * LMK + t] = sZ[t];
    }
}

// =========================================================================
// 6) combine partials -> F, then G = kinv @ F. 8 blocks x 256 threads.
// =========================================================================
__global__ void __launch_bounds__(256) k_combine() {
    __shared__ float sWt[NCH * LMK];
    __shared__ float sF[LMK * DH];
    const int b = blockIdx.x, t = threadIdx.x;
    if (t < 64) {
        int l = t;
        float M = -1e30f;
        for (int c = 0; c < NCH; c++) M = fmaxf(M, g_pm[(b * NCH + c) * LMK + l]);
        float Z = 0.f;
        for (int c = 0; c < NCH; c++)
            Z += g_pz[(b * NCH + c) * LMK + l] * __expf(g_pm[(b * NCH + c) * LMK + l] - M);
        float rZ = 1.f / Z;
        for (int c = 0; c < NCH; c++)
            sWt[c * LMK + l] = __expf(g_pm[(b * NCH + c) * LMK + l] - M) * rZ;
    }
    __syncthreads();
    const int d = t & 127, half = t >> 7;
    for (int la = 0; la < 32; la++) {
        int l = half * 32 + la;
        float acc = 0.f;
        for (int c = 0; c < NCH; c++)
            acc += g_ps[(((long)(b * NCH + c)) * LMK + l) * DH + d] * sWt[c * LMK + l];
        sF[l * DH + d] = acc;
    }
    __syncthreads();
    const float* inv = g_kinv + b * 4096;
    for (int la = 0; la < 32; la++) {
        int l = half * 32 + la;
        float acc = 0.f;
        for (int j = 0; j < 64; j++) acc += inv[l * 64 + j] * sF[j * DH + d];
        g_G[((long)b * LMK + l) * DH + d] = acc;
    }
}

// =========================================================================
// 7) fused epilogue: kernel_1 softmax -> @G -> proj -> +bias -> +v residual.
// =========================================================================
__global__ void __launch_bounds__(256) k_out(const float* __restrict__ pb,
                                             float* __restrict__ out) {
    __shared__ float sQ[LMK * DH];   // q tile, later reused for o
    __shared__ float sP[LMK * LMK];
    const int bid = blockIdx.x;
    const int b = bid >> 7;
    const int n0 = (bid & 127) * 64;
    const int t = threadIdx.x;
    const long rowbase = (long)b * SEQL + n0;

    for (int e = t; e < LMK * DH; e += 256) sQ[e] = g_q[rowbase * DH + e];
    __syncthreads();
    {
        const int l = t & 63, rg = t >> 6;
        const float* krow = g_klm + ((long)b * LMK + l) * DH;
        float s[16];
#pragma unroll
        for (int r = 0; r < 16; r++) s[r] = 0.f;
        for (int d4 = 0; d4 < DH; d4 += 4) {
            float4 kv = *(const float4*)(krow + d4);
#pragma unroll
            for (int r = 0; r < 16; r++) {
                float4 qv = *(const float4*)&sQ[(rg * 16 + r) * DH + d4];
                s[r] += qv.x*kv.x + qv.y*kv.y + qv.z*kv.z + qv.w*kv.w;
            }
        }
#pragma unroll
        for (int r = 0; r < 16; r++) sP[(rg * 16 + r) * 64 + l] = s[r];
    }
    __syncthreads();
    {
        const int w = t >> 5, lane = t & 31;
        for (int rr = 0; rr < 8; rr++) {
            int r = w * 8 + rr;
            float v0 = sP[r * 64 + lane], v1 = sP[r * 64 + 32 + lane];
            float m = fmaxf(v0, v1);
            for (int o = 16; o; o >>= 1) m = fmaxf(m, __shfl_xor_sync(0xffffffffu, m, o));
            v0 = __expf(v0 - m); v1 = __expf(v1 - m);
            float s = v0 + v1;
            for (int o = 16; o; o >>= 1) s += __shfl_xor_sync(0xffffffffu, s, o);
            float inv = 1.f / s;
            sP[r * 64 + lane] = v0 * inv;
            sP[r * 64 + 32 + lane] = v1 * inv;
        }
    }
    __syncthreads();
    const int d = t & 127, half = t >> 7;
    float o[32];
#pragma unroll
    for (int la = 0; la < 32; la++) o[la] = 0.f;
    const float* Gb = g_G + (long)b * LMK * DH;
    for (int l4 = 0; l4 < 64; l4 += 4) {
        float g0 = Gb[(l4 + 0) * DH + d];
        float g1 = Gb[(l4 + 1) * DH + d];
        float g2 = Gb[(l4 + 2) * DH + d];
        float g3 = Gb[(l4 + 3) * DH + d];
#pragma unroll
        for (int la = 0; la < 32; la++) {
            float4 pv = *(float4*)&sP[(half * 32 + la) * 64 + l4];
            o[la] += pv.x * g0 + pv.y * g1 + pv.z * g2 + pv.w * g3;
        }
    }
    __syncthreads();
#pragma unroll
    for (int la = 0; la < 32; la++) sQ[(half * 32 + la) * DH + d] = o[la];
    __syncthreads();
    float y[32];
#pragma unroll
    for (int la = 0; la < 32; la++) y[la] = 0.f;
    for (int e4 = 0; e4 < DH; e4 += 4) {
        float w0 = g_pwT[(e4 + 0) * DH + d];
        float w1 = g_pwT[(e4 + 1) * DH + d];
        float w2 = g_pwT[(e4 + 2) * DH + d];
        float w3 = g_pwT[(e4 + 3) * DH + d];
#pragma unroll
        for (int la = 0; la < 32; la++) {
            float4 ov = *(float4*)&sQ[(half * 32 + la) * DH + e4];
            y[la] += ov.x * w0 + ov.y * w1 + ov.z * w2 + ov.w * w3;
        }
    }
    const float bias = pb[d];
#pragma unroll
    for (int la = 0; la < 32; la++) {
        long n = rowbase + half * 32 + la;
        out[n * DH + d] = g_v[n * DH + d] + y[la] + bias;
    }
}

// =========================================================================
// Launch: single stream, no stream/event API — graph-capture identical in
// structure to the known-good R4 config. Newton hides inside k_mid's grid.
// =========================================================================
extern "C" void kernel_launch(void* const* d_in, const int* in_sizes, int n_in,
                              void* d_out, int out_size) {
    const float* x      = (const float*)d_in[0];
    const float* qkv_w  = (const float*)d_in[1];
    const float* proj_w = (const float*)d_in[2];
    const float* proj_b = (const float*)d_in[3];
    float* out = (float*)d_out;

    k_qkv<<<dim3(512, 3), 256>>>(x, qkv_w);
    k_lm<<<512, 128>>>();
    k_pwT<<<128, 128>>>(proj_w);
    k_mid<<<dim3(8, NCH + 1), 256, 49152>>>();
    k_combine<<<8, 256>>>();
    k_out<<<1024, 256>>>(proj_b, out);
}